// round 6
// baseline (speedup 1.0000x reference)
#include <cuda_runtime.h>

#define BSZ 64
#define ICAPS 8192
#define JCAPS 8
#define NDIM 8
#define MDIM 16

#define CI 8
#define NCHUNKS (ICAPS / CI)       /* 1024 */
#define THREADS 512

#define W_FLOATS (CI * 1024)       /* 8192 per buffer: [ci][n][j^(n&1)][m16] */
#define X_STRIDE 132               /* duplicated x row: 128 data + 4 pad (528 B) */
#define X_FLOATS (BSZ * X_STRIDE)  /* 8448 */
#define SMEM_FLOATS (2 * W_FLOATS + X_FLOATS)       /* 24832 */
#define SMEM_BYTES (SMEM_FLOATS * 4)                /* 99328 B -> 1 CTA/SM */

__device__ float g_s[3][BSZ * JCAPS * MDIM];   // stage-wise s accumulators

typedef unsigned long long u64;

__device__ __forceinline__ u64 pk2(float a, float b) {
    u64 r; asm("mov.b64 %0, {%1, %2};" : "=l"(r) : "f"(a), "f"(b)); return r;
}
__device__ __forceinline__ void upk2(u64 v, float& a, float& b) {
    asm("mov.b64 {%0, %1}, %2;" : "=f"(a), "=f"(b) : "l"(v));
}
__device__ __forceinline__ u64 mul2(u64 a, u64 b) {
    u64 r; asm("mul.rn.f32x2 %0, %1, %2;" : "=l"(r) : "l"(a), "l"(b)); return r;
}
__device__ __forceinline__ void fma2(u64& d, u64 a, u64 b) {
    asm("fma.rn.f32x2 %0, %1, %2, %0;" : "+l"(d) : "l"(a), "l"(b));
}
__device__ __forceinline__ void lds2(u64& a, u64& b, unsigned addr) {
    asm volatile("ld.shared.v2.b64 {%0, %1}, [%2];" : "=l"(a), "=l"(b) : "r"(addr));
}
__device__ __forceinline__ void cpasync16(unsigned dst, const void* src) {
    asm volatile("cp.async.cg.shared.global [%0], [%1], 16;" :: "r"(dst), "l"(src));
}
__device__ __forceinline__ void cpcommit() { asm volatile("cp.async.commit_group;"); }
__device__ __forceinline__ void cpwait0()  { asm volatile("cp.async.wait_group 0;" ::: "memory"); }

// Stage one chunk's W via cp.async with transpose+swizzle scatter (validated R4/R5).
// global [ci][j][n][m16] -> smem [ci][n][j^(n&1)][m16].
__device__ __forceinline__ void stage_W_async(unsigned wbuf, const float* __restrict__ W,
                                              int ch, int tid)
{
    const float* src = W + (size_t)ch * W_FLOATS;
    #pragma unroll
    for (int q = 0; q < 4; q++) {
        const int idx = (tid + q * THREADS) * 4;
        const int ci = idx >> 10;
        const int r  = idx & 1023;
        const int j  = r >> 7;
        const int n  = (r >> 4) & 7;
        const int m  = r & 15;
        const unsigned dst = wbuf +
            (unsigned)((ci << 10) + (n << 7) + (((j ^ (n & 1))) << 4) + m) * 4u;
        cpasync16(dst, src + idx);
    }
}

// Shared chunk-loop scaffolding: stages W (double-buffered cp.async) and dup-x,
// calls BODY(wbuf_byte_base) for each chunk. Implemented as a macro-free template.
template <class Body>
__device__ __forceinline__ void chunk_loop(const float* __restrict__ x,
                                           const float* __restrict__ W,
                                           float* xs, unsigned shbase,
                                           int tid, Body body)
{
    int ch = blockIdx.x;
    int p  = 0;
    float4 xreg[2];
    stage_W_async(shbase, W, ch, tid);
    cpcommit();
    #pragma unroll
    for (int q = 0; q < 2; q++) {
        const int idx4 = tid + q * THREADS;
        const int b = idx4 >> 4;
        const int k = (idx4 & 15) * 4;
        xreg[q] = __ldcg(reinterpret_cast<const float4*>(
            &x[(size_t)b * (ICAPS * NDIM) + (size_t)ch * (CI * NDIM) + k]));
    }
    bool first = true;

    while (true) {
        if (!first) __syncthreads();
        cpwait0();
        #pragma unroll
        for (int q = 0; q < 2; q++) {
            const int idx4 = tid + q * THREADS;
            const int b = idx4 >> 4;
            const int k = (idx4 & 15) * 4;
            float* d = xs + b * X_STRIDE + 2 * k;
            *reinterpret_cast<float4*>(d)     = make_float4(xreg[q].x, xreg[q].x, xreg[q].y, xreg[q].y);
            *reinterpret_cast<float4*>(d + 4) = make_float4(xreg[q].z, xreg[q].z, xreg[q].w, xreg[q].w);
        }
        __syncthreads();

        const int chn = ch + (int)gridDim.x;
        const bool have_next = (chn < NCHUNKS);
        if (have_next) {
            stage_W_async(shbase + (unsigned)(p ^ 1) * (W_FLOATS * 4u), W, chn, tid);
            cpcommit();
            #pragma unroll
            for (int q = 0; q < 2; q++) {
                const int idx4 = tid + q * THREADS;
                const int b = idx4 >> 4;
                const int k = (idx4 & 15) * 4;
                xreg[q] = __ldcg(reinterpret_cast<const float4*>(
                    &x[(size_t)b * (ICAPS * NDIM) + (size_t)chn * (CI * NDIM) + k]));
            }
        }

        body(shbase + (unsigned)p * (W_FLOATS * 4u));

        if (!have_next) break;
        ch = chn;
        p ^= 1;
        first = false;
    }
}

// ---------------- Stage 0: c == 1/8 exactly -> pure contraction, no routing ----------------
__global__ __launch_bounds__(THREADS, 1)
void stage0_kernel(const float* __restrict__ x, const float* __restrict__ W)
{
    extern __shared__ float sh[];
    float* xs = sh + 2 * W_FLOATS;

    const int tid  = threadIdx.x;
    const int lane = tid & 31;
    const int w    = tid >> 5;
    const int j    = lane & 7;          // out-cap
    const int bq   = (lane >> 3) & 1;   // batch-in-lane
    const int mh   = lane >> 4;         // m-half: m in [mh*8, mh*8+8)
    const int b0   = w * 4;             // batches b0 + bbl*2 + bq

    const unsigned shbase = (unsigned)__cvta_generic_to_shared(sh);
    const unsigned xsbase = shbase + 2u * W_FLOATS * 4u;
    const unsigned wofs_e = (unsigned)(j * 64 + mh * 32);          // even n
    const unsigned wofs_o = (unsigned)((j ^ 1) * 64 + mh * 32);    // odd n (XOR swizzle)

    u64 sacc[2][4];
    #pragma unroll
    for (int l = 0; l < 2; l++)
        #pragma unroll
        for (int pq = 0; pq < 4; pq++) sacc[l][pq] = 0ull;

    chunk_loop(x, W, xs, shbase, tid, [&](unsigned wb) {
        const unsigned we = wb + wofs_e;
        const unsigned wo = wb + wofs_o;
        #pragma unroll 1
        for (int ii = 0; ii < CI; ++ii) {
            const unsigned xa0 = xsbase + (unsigned)((b0 + 0 + bq) * X_STRIDE + ii * 16) * 4u;
            const unsigned xa1 = xsbase + (unsigned)((b0 + 2 + bq) * X_STRIDE + ii * 16) * 4u;
            const unsigned ae = we + (unsigned)(ii * 4096);
            const unsigned ao = wo + (unsigned)(ii * 4096);
            #pragma unroll
            for (int n2 = 0; n2 < 4; n2++) {
                u64 x0a, x0b, x1a, x1b;
                lds2(x0a, x0b, xa0 + n2 * 16);   // (x_{2n2},x_{2n2}), (x_{2n2+1},..) for bbl=0
                lds2(x1a, x1b, xa1 + n2 * 16);
                u64 we0, we1, we2, we3, wo0, wo1, wo2, wo3;
                lds2(we0, we1, ae + (2 * n2) * 512);
                lds2(we2, we3, ae + (2 * n2) * 512 + 16);
                lds2(wo0, wo1, ao + (2 * n2 + 1) * 512);
                lds2(wo2, wo3, ao + (2 * n2 + 1) * 512 + 16);
                fma2(sacc[0][0], we0, x0a); fma2(sacc[0][1], we1, x0a);
                fma2(sacc[0][2], we2, x0a); fma2(sacc[0][3], we3, x0a);
                fma2(sacc[0][0], wo0, x0b); fma2(sacc[0][1], wo1, x0b);
                fma2(sacc[0][2], wo2, x0b); fma2(sacc[0][3], wo3, x0b);
                fma2(sacc[1][0], we0, x1a); fma2(sacc[1][1], we1, x1a);
                fma2(sacc[1][2], we2, x1a); fma2(sacc[1][3], we3, x1a);
                fma2(sacc[1][0], wo0, x1b); fma2(sacc[1][1], wo1, x1b);
                fma2(sacc[1][2], wo2, x1b); fma2(sacc[1][3], wo3, x1b);
            }
        }
    });

    float* sout = &g_s[0][0];
    #pragma unroll
    for (int l = 0; l < 2; l++) {
        const int b = b0 + l * 2 + bq;
        const int base = (b * JCAPS + j) * MDIM + mh * 8;
        #pragma unroll
        for (int pq = 0; pq < 4; pq++) {
            float lo, hi; upk2(sacc[l][pq], lo, hi);
            atomicAdd(&sout[base + 2 * pq],     0.125f * lo);
            atomicAdd(&sout[base + 2 * pq + 1], 0.125f * hi);
        }
    }
}

// ---------------- Stages 1,2: full routing, (mh,bq,j) layout ----------------
__global__ __launch_bounds__(THREADS, 1)
void route_kernel(const float* __restrict__ x, const float* __restrict__ W, int stage)
{
    extern __shared__ float sh[];
    float* xs = sh + 2 * W_FLOATS;

    const int tid  = threadIdx.x;
    const int lane = tid & 31;
    const int w    = tid >> 5;
    const int j    = lane & 7;
    const int bq   = (lane >> 3) & 1;
    const int mh   = lane >> 4;
    const int b0   = w * 4;

    // vsum = sum_{st<stage} squash(g_s[st]) for lane's (2 batches, j, m-half)
    u64 vp[2][4];
    #pragma unroll
    for (int l = 0; l < 2; l++) {
        const int b = b0 + l * 2 + bq;
        float v[8];
        #pragma unroll
        for (int m = 0; m < 8; m++) v[m] = 0.0f;
        for (int st = 0; st < stage; ++st) {
            const float* sp = &g_s[st][(b * JCAPS + j) * MDIM + mh * 8];
            const float4 t0 = __ldcg(reinterpret_cast<const float4*>(sp));
            const float4 t1 = __ldcg(reinterpret_cast<const float4*>(sp + 4));
            float sv[8] = {t0.x, t0.y, t0.z, t0.w, t1.x, t1.y, t1.z, t1.w};
            float sq = 0.0f;
            #pragma unroll
            for (int m = 0; m < 8; m++) sq = fmaf(sv[m], sv[m], sq);
            sq += __shfl_xor_sync(0xffffffffu, sq, 16);   // add other m-half -> full norm^2
            const float sc = sqrtf(sq) / (1.0f + sq);
            #pragma unroll
            for (int m = 0; m < 8; m++) v[m] = fmaf(sc, sv[m], v[m]);
        }
        #pragma unroll
        for (int pq = 0; pq < 4; pq++) vp[l][pq] = pk2(v[2 * pq], v[2 * pq + 1]);
    }

    u64 sacc[2][4];
    #pragma unroll
    for (int l = 0; l < 2; l++)
        #pragma unroll
        for (int pq = 0; pq < 4; pq++) sacc[l][pq] = 0ull;

    const unsigned shbase = (unsigned)__cvta_generic_to_shared(sh);
    const unsigned xsbase = shbase + 2u * W_FLOATS * 4u;
    const unsigned wofs_e = (unsigned)(j * 64 + mh * 32);
    const unsigned wofs_o = (unsigned)((j ^ 1) * 64 + mh * 32);

    chunk_loop(x, W, xs, shbase, tid, [&](unsigned wb) {
        const unsigned we = wb + wofs_e;
        const unsigned wo = wb + wofs_o;
        #pragma unroll 1
        for (int ii = 0; ii < CI; ++ii) {
            const unsigned xa0 = xsbase + (unsigned)((b0 + 0 + bq) * X_STRIDE + ii * 16) * 4u;
            const unsigned xa1 = xsbase + (unsigned)((b0 + 2 + bq) * X_STRIDE + ii * 16) * 4u;
            const unsigned ae = we + (unsigned)(ii * 4096);
            const unsigned ao = wo + (unsigned)(ii * 4096);

            u64 uh[2][4];
            {   // n = 0 (mul) and n = 1 (fma)
                u64 x0a, x0b, x1a, x1b;
                lds2(x0a, x0b, xa0);
                lds2(x1a, x1b, xa1);
                u64 we0, we1, we2, we3, wo0, wo1, wo2, wo3;
                lds2(we0, we1, ae);       lds2(we2, we3, ae + 16);
                lds2(wo0, wo1, ao + 512); lds2(wo2, wo3, ao + 512 + 16);
                uh[0][0] = mul2(we0, x0a); uh[0][1] = mul2(we1, x0a);
                uh[0][2] = mul2(we2, x0a); uh[0][3] = mul2(we3, x0a);
                uh[1][0] = mul2(we0, x1a); uh[1][1] = mul2(we1, x1a);
                uh[1][2] = mul2(we2, x1a); uh[1][3] = mul2(we3, x1a);
                fma2(uh[0][0], wo0, x0b); fma2(uh[0][1], wo1, x0b);
                fma2(uh[0][2], wo2, x0b); fma2(uh[0][3], wo3, x0b);
                fma2(uh[1][0], wo0, x1b); fma2(uh[1][1], wo1, x1b);
                fma2(uh[1][2], wo2, x1b); fma2(uh[1][3], wo3, x1b);
            }
            #pragma unroll
            for (int n2 = 1; n2 < 4; n2++) {
                u64 x0a, x0b, x1a, x1b;
                lds2(x0a, x0b, xa0 + n2 * 16);
                lds2(x1a, x1b, xa1 + n2 * 16);
                u64 we0, we1, we2, we3, wo0, wo1, wo2, wo3;
                lds2(we0, we1, ae + (2 * n2) * 512);
                lds2(we2, we3, ae + (2 * n2) * 512 + 16);
                lds2(wo0, wo1, ao + (2 * n2 + 1) * 512);
                lds2(wo2, wo3, ao + (2 * n2 + 1) * 512 + 16);
                fma2(uh[0][0], we0, x0a); fma2(uh[0][1], we1, x0a);
                fma2(uh[0][2], we2, x0a); fma2(uh[0][3], we3, x0a);
                fma2(uh[1][0], we0, x1a); fma2(uh[1][1], we1, x1a);
                fma2(uh[1][2], we2, x1a); fma2(uh[1][3], we3, x1a);
                fma2(uh[0][0], wo0, x0b); fma2(uh[0][1], wo1, x0b);
                fma2(uh[0][2], wo2, x0b); fma2(uh[0][3], wo3, x0b);
                fma2(uh[1][0], wo0, x1b); fma2(uh[1][1], wo1, x1b);
                fma2(uh[1][2], wo2, x1b); fma2(uh[1][3], wo3, x1b);
            }

            // routing for both bbl (softmax shuffles serve 2 (b,i) each)
            #pragma unroll
            for (int l = 0; l < 2; l++) {
                u64 pp = mul2(uh[l][0], vp[l][0]);
                fma2(pp, uh[l][1], vp[l][1]);
                fma2(pp, uh[l][2], vp[l][2]);
                fma2(pp, uh[l][3], vp[l][3]);
                float plo, phi; upk2(pp, plo, phi);
                float pl = plo + phi;
                pl += __shfl_xor_sync(0xffffffffu, pl, 16);   // other m-half -> full dot
                const float e = __expf(pl);                   // |logit| < 1: no max needed
                float sm = e;
                sm += __shfl_xor_sync(0xffffffffu, sm, 1);
                sm += __shfl_xor_sync(0xffffffffu, sm, 2);
                sm += __shfl_xor_sync(0xffffffffu, sm, 4);    // sum over j
                const float c = __fdividef(e, sm);
                const u64 c2 = pk2(c, c);
                fma2(sacc[l][0], c2, uh[l][0]);
                fma2(sacc[l][1], c2, uh[l][1]);
                fma2(sacc[l][2], c2, uh[l][2]);
                fma2(sacc[l][3], c2, uh[l][3]);
            }
        }
    });

    float* sout = &g_s[stage][0];
    #pragma unroll
    for (int l = 0; l < 2; l++) {
        const int b = b0 + l * 2 + bq;
        const int base = (b * JCAPS + j) * MDIM + mh * 8;
        #pragma unroll
        for (int pq = 0; pq < 4; pq++) {
            float lo, hi; upk2(sacc[l][pq], lo, hi);
            atomicAdd(&sout[base + 2 * pq],     lo);
            atomicAdd(&sout[base + 2 * pq + 1], hi);
        }
    }
}

// out = squash(s3)
__global__ void final_squash_kernel(float* __restrict__ out)
{
    const int t = blockIdx.x * blockDim.x + threadIdx.x;
    const int b = t >> 3;
    const int j = t & 7;
    const float* sp = &g_s[2][(b * JCAPS + j) * MDIM];
    float sv[MDIM];
    float sn = 0.0f;
    #pragma unroll
    for (int q = 0; q < 4; q++) {
        const float4 tt = __ldcg(reinterpret_cast<const float4*>(sp + q * 4));
        sv[q*4+0] = tt.x; sv[q*4+1] = tt.y; sv[q*4+2] = tt.z; sv[q*4+3] = tt.w;
    }
    #pragma unroll
    for (int m = 0; m < MDIM; m++) sn = fmaf(sv[m], sv[m], sn);
    const float scale = sqrtf(sn) / (1.0f + sn);
    #pragma unroll
    for (int m = 0; m < MDIM; m++) out[(b * JCAPS + j) * MDIM + m] = scale * sv[m];
}

extern "C" void kernel_launch(void* const* d_in, const int* in_sizes, int n_in,
                              void* d_out, int out_size)
{
    const float* x = (const float*)d_in[0];
    const float* W = (const float*)d_in[1];
    if (n_in >= 2 && in_sizes[0] == 8388608 && in_sizes[1] == 4194304) {
        x = (const float*)d_in[1];
        W = (const float*)d_in[0];
    }

    int dev = 0;
    cudaGetDevice(&dev);
    int sm = 148;
    cudaDeviceGetAttribute(&sm, cudaDevAttrMultiProcessorCount, dev);
    if (sm < 1) sm = 1;
    if (sm > 512) sm = 512;

    cudaFuncSetAttribute(stage0_kernel, cudaFuncAttributeMaxDynamicSharedMemorySize, SMEM_BYTES);
    cudaFuncSetAttribute(route_kernel,  cudaFuncAttributeMaxDynamicSharedMemorySize, SMEM_BYTES);

    void* sptr = nullptr;
    cudaGetSymbolAddress(&sptr, g_s);
    cudaMemsetAsync(sptr, 0, sizeof(float) * 3 * BSZ * JCAPS * MDIM);

    stage0_kernel<<<sm, THREADS, SMEM_BYTES>>>(x, W);
    route_kernel<<<sm, THREADS, SMEM_BYTES>>>(x, W, 1);
    route_kernel<<<sm, THREADS, SMEM_BYTES>>>(x, W, 2);
    final_squash_kernel<<<16, 32>>>((float*)d_out);
}

// round 7
// speedup vs baseline: 2.6710x; 2.6710x over previous
#include <cuda_runtime.h>

#define BSZ 64
#define ICAPS 8192
#define JCAPS 8
#define NDIM 8
#define MDIM 16

#define CI 8
#define NCHUNKS (ICAPS / CI)       /* 1024 */
#define THREADS 512

#define W_FLOATS (CI * 1024)       /* 8192 per buffer: [ci][n][j^(n&1)][m16] */
#define X_STRIDE 132               /* duplicated x row: 128 data + 4 pad */
#define X_FLOATS (BSZ * X_STRIDE)  /* 8448 */
#define SMEM_FLOATS (2 * W_FLOATS + X_FLOATS)       /* 24832 */
#define SMEM_BYTES (SMEM_FLOATS * 4)                /* 99328 B -> 1 CTA/SM */

__device__ float g_s[3][BSZ * JCAPS * MDIM];   // stage-wise s accumulators

typedef unsigned long long u64;

__device__ __forceinline__ u64 pk2(float a, float b) {
    u64 r; asm("mov.b64 %0, {%1, %2};" : "=l"(r) : "f"(a), "f"(b)); return r;
}
__device__ __forceinline__ void upk2(u64 v, float& a, float& b) {
    asm("mov.b64 {%0, %1}, %2;" : "=f"(a), "=f"(b) : "l"(v));
}
__device__ __forceinline__ u64 mul2(u64 a, u64 b) {
    u64 r; asm("mul.rn.f32x2 %0, %1, %2;" : "=l"(r) : "l"(a), "l"(b)); return r;
}
__device__ __forceinline__ void fma2(u64& d, u64 a, u64 b) {
    asm("fma.rn.f32x2 %0, %1, %2, %0;" : "+l"(d) : "l"(a), "l"(b));
}
__device__ __forceinline__ void add2(u64& d, u64 a) {
    asm("add.rn.f32x2 %0, %1, %0;" : "+l"(d) : "l"(a));
}
__device__ __forceinline__ void lds2(u64& a, u64& b, unsigned addr) {
    asm volatile("ld.shared.v2.b64 {%0, %1}, [%2];" : "=l"(a), "=l"(b) : "r"(addr));
}
__device__ __forceinline__ void cpasync16(unsigned dst, const void* src) {
    asm volatile("cp.async.cg.shared.global [%0], [%1], 16;" :: "r"(dst), "l"(src));
}
__device__ __forceinline__ void cpcommit() { asm volatile("cp.async.commit_group;"); }
__device__ __forceinline__ void cpwait0()  { asm volatile("cp.async.wait_group 0;" ::: "memory"); }

// Stage one chunk's W via cp.async with transpose+swizzle scatter (validated R4/R5).
// global [ci][j][n][m16] -> smem [ci][n][j^(n&1)][m16].
__device__ __forceinline__ void stage_W_async(unsigned wbuf, const float* __restrict__ W,
                                              int ch, int tid)
{
    const float* src = W + (size_t)ch * W_FLOATS;
    #pragma unroll
    for (int q = 0; q < 4; q++) {
        const int idx = (tid + q * THREADS) * 4;      // float index, 16B granule
        const int ci = idx >> 10;
        const int r  = idx & 1023;
        const int j  = r >> 7;
        const int n  = (r >> 4) & 7;
        const int m  = r & 15;                        // 0,4,8,12
        const unsigned dst = wbuf +
            (unsigned)((ci << 10) + (n << 7) + (((j ^ (n & 1))) << 4) + m) * 4u;
        cpasync16(dst, src + idx);
    }
}

// STAGE: 0 -> uniform-c contraction (no routing); 1,2 -> full routing.
template <int STAGE>
__global__ __launch_bounds__(THREADS, 1)
void route_kernel(const float* __restrict__ x, const float* __restrict__ W)
{
    extern __shared__ float sh[];
    float* xs = sh + 2 * W_FLOATS;

    const int tid  = threadIdx.x;
    const int lane = tid & 31;
    const int w    = tid >> 5;
    const int j    = lane >> 2;     // out-cap 0..7
    const int mq   = lane & 3;      // m-quad 0..3
    const int b0   = w * 4;         // warp owns batches b0..b0+3

    // ---- vsum = sum_{st<STAGE} squash(g_s[st]) for this lane's (4 batches, j, mq) ----
    u64 vp[4][2];
    if (STAGE > 0) {
        #pragma unroll
        for (int bb = 0; bb < 4; bb++) {
            float v0 = 0.f, v1 = 0.f, v2v = 0.f, v3 = 0.f;
            #pragma unroll
            for (int st = 0; st < STAGE; ++st) {
                const float4 s4 = __ldcg(reinterpret_cast<const float4*>(
                    &g_s[st][((b0 + bb) * JCAPS + j) * MDIM + mq * 4]));
                float sq = s4.x * s4.x;
                sq = fmaf(s4.y, s4.y, sq);
                sq = fmaf(s4.z, s4.z, sq);
                sq = fmaf(s4.w, s4.w, sq);
                sq += __shfl_xor_sync(0xffffffffu, sq, 1);
                sq += __shfl_xor_sync(0xffffffffu, sq, 2);   // norm^2 over all 16 m
                const float sc = sqrtf(sq) / (1.0f + sq);    // squash scale
                v0 = fmaf(sc, s4.x, v0); v1 = fmaf(sc, s4.y, v1);
                v2v = fmaf(sc, s4.z, v2v); v3 = fmaf(sc, s4.w, v3);
            }
            vp[bb][0] = pk2(v0, v1);
            vp[bb][1] = pk2(v2v, v3);
        }
    }

    u64 sacc[4][2];
    #pragma unroll
    for (int bb = 0; bb < 4; bb++) { sacc[bb][0] = 0ull; sacc[bb][1] = 0ull; }

    const unsigned shbase = (unsigned)__cvta_generic_to_shared(sh);
    const unsigned xsbase = shbase + 2u * W_FLOATS * 4u;
    const unsigned wofs_e = (unsigned)((j * 16) + mq * 4) * 4u;        // even n
    const unsigned wofs_o = (unsigned)(((j ^ 1) * 16) + mq * 4) * 4u;  // odd n (XOR swizzle)

    // ---- double-buffered-W chunk loop (identical to validated R5) ----
    int ch = blockIdx.x;
    int p  = 0;
    float4 xreg[2];
    stage_W_async(shbase, W, ch, tid);
    cpcommit();
    #pragma unroll
    for (int q = 0; q < 2; q++) {
        const int idx4 = tid + q * THREADS;
        const int b = idx4 >> 4;
        const int k = (idx4 & 15) * 4;
        xreg[q] = __ldcg(reinterpret_cast<const float4*>(
            &x[(size_t)b * (ICAPS * NDIM) + (size_t)ch * (CI * NDIM) + k]));
    }
    bool first = true;

    while (true) {
        if (!first) __syncthreads();
        cpwait0();
        #pragma unroll
        for (int q = 0; q < 2; q++) {
            const int idx4 = tid + q * THREADS;
            const int b = idx4 >> 4;
            const int k = (idx4 & 15) * 4;
            float* d = xs + b * X_STRIDE + 2 * k;
            *reinterpret_cast<float4*>(d)     = make_float4(xreg[q].x, xreg[q].x, xreg[q].y, xreg[q].y);
            *reinterpret_cast<float4*>(d + 4) = make_float4(xreg[q].z, xreg[q].z, xreg[q].w, xreg[q].w);
        }
        __syncthreads();

        const int chn = ch + (int)gridDim.x;
        const bool have_next = (chn < NCHUNKS);
        if (have_next) {
            stage_W_async(shbase + (unsigned)(p ^ 1) * (W_FLOATS * 4u), W, chn, tid);
            cpcommit();
            #pragma unroll
            for (int q = 0; q < 2; q++) {
                const int idx4 = tid + q * THREADS;
                const int b = idx4 >> 4;
                const int k = (idx4 & 15) * 4;
                xreg[q] = __ldcg(reinterpret_cast<const float4*>(
                    &x[(size_t)b * (ICAPS * NDIM) + (size_t)chn * (CI * NDIM) + k]));
            }
        }

        // ---- compute this chunk (buffer p) ----
        const unsigned wb = shbase + (unsigned)p * (W_FLOATS * 4u);
        const unsigned we = wb + wofs_e;
        const unsigned wo = wb + wofs_o;

        #pragma unroll 1
        for (int ii = 0; ii < CI; ++ii) {
            u64 wp[8][2];
            #pragma unroll
            for (int n = 0; n < 8; n++) {
                const unsigned a = ((n & 1) ? wo : we) + (unsigned)(ii * 4096 + n * 512);
                lds2(wp[n][0], wp[n][1], a);
            }
            #pragma unroll
            for (int bb = 0; bb < 4; bb++) {
                const unsigned xa = xsbase + (unsigned)((b0 + bb) * X_STRIDE + ii * 16) * 4u;
                u64 xq[8];
                lds2(xq[0], xq[1], xa);          // broadcast loads
                lds2(xq[2], xq[3], xa + 16);
                lds2(xq[4], xq[5], xa + 32);
                lds2(xq[6], xq[7], xa + 48);

                u64 uh0 = mul2(wp[0][0], xq[0]);
                u64 uh1 = mul2(wp[0][1], xq[0]);
                #pragma unroll
                for (int n = 1; n < 8; n++) {
                    fma2(uh0, wp[n][0], xq[n]);
                    fma2(uh1, wp[n][1], xq[n]);
                }

                if (STAGE == 0) {
                    // b == 0 -> c exactly 1/8 for all j: plain accumulation, scaled at flush
                    add2(sacc[bb][0], uh0);
                    add2(sacc[bb][1], uh1);
                } else {
                    // logit = dot(vsum, u_hat); |logit| < 1 so no max subtraction
                    u64 pp = mul2(uh0, vp[bb][0]);
                    fma2(pp, uh1, vp[bb][1]);
                    float plo, phi; upk2(pp, plo, phi);
                    float pl = plo + phi;
                    pl += __shfl_xor_sync(0xffffffffu, pl, 1);
                    pl += __shfl_xor_sync(0xffffffffu, pl, 2);
                    const float e = __expf(pl);
                    float sm = e;
                    sm += __shfl_xor_sync(0xffffffffu, sm, 4);
                    sm += __shfl_xor_sync(0xffffffffu, sm, 8);
                    sm += __shfl_xor_sync(0xffffffffu, sm, 16);
                    const float c = __fdividef(e, sm);
                    const u64 c2 = pk2(c, c);
                    fma2(sacc[bb][0], c2, uh0);
                    fma2(sacc[bb][1], c2, uh1);
                }
            }
        }

        if (!have_next) break;
        ch = chn;
        p ^= 1;
        first = false;
    }

    // ---- flush this warp's disjoint (b, j, mq) partials ----
    const float scale = (STAGE == 0) ? 0.125f : 1.0f;
    float* sout = &g_s[STAGE][0];
    #pragma unroll
    for (int bb = 0; bb < 4; bb++) {
        const int base = ((b0 + bb) * JCAPS + j) * MDIM + mq * 4;
        float a0, a1, a2, a3;
        upk2(sacc[bb][0], a0, a1);
        upk2(sacc[bb][1], a2, a3);
        atomicAdd(&sout[base + 0], scale * a0);
        atomicAdd(&sout[base + 1], scale * a1);
        atomicAdd(&sout[base + 2], scale * a2);
        atomicAdd(&sout[base + 3], scale * a3);
    }
}

// out = squash(s3)
__global__ void final_squash_kernel(float* __restrict__ out)
{
    const int t = blockIdx.x * blockDim.x + threadIdx.x;   // 0..511
    const int b = t >> 3;
    const int j = t & 7;
    const float* sp = &g_s[2][(b * JCAPS + j) * MDIM];
    float sv[MDIM];
    float sn = 0.0f;
    #pragma unroll
    for (int q = 0; q < 4; q++) {
        const float4 tt = __ldcg(reinterpret_cast<const float4*>(sp + q * 4));
        sv[q*4+0] = tt.x; sv[q*4+1] = tt.y; sv[q*4+2] = tt.z; sv[q*4+3] = tt.w;
    }
    #pragma unroll
    for (int m = 0; m < MDIM; m++) sn = fmaf(sv[m], sv[m], sn);
    const float scale = sqrtf(sn) / (1.0f + sn);
    #pragma unroll
    for (int m = 0; m < MDIM; m++) out[(b * JCAPS + j) * MDIM + m] = scale * sv[m];
}

extern "C" void kernel_launch(void* const* d_in, const int* in_sizes, int n_in,
                              void* d_out, int out_size)
{
    const float* x = (const float*)d_in[0];
    const float* W = (const float*)d_in[1];
    if (n_in >= 2 && in_sizes[0] == 8388608 && in_sizes[1] == 4194304) {
        x = (const float*)d_in[1];
        W = (const float*)d_in[0];
    }

    int dev = 0;
    cudaGetDevice(&dev);
    int sm = 148;
    cudaDeviceGetAttribute(&sm, cudaDevAttrMultiProcessorCount, dev);
    if (sm < 1) sm = 1;
    if (sm > 512) sm = 512;

    cudaFuncSetAttribute(route_kernel<0>, cudaFuncAttributeMaxDynamicSharedMemorySize, SMEM_BYTES);
    cudaFuncSetAttribute(route_kernel<1>, cudaFuncAttributeMaxDynamicSharedMemorySize, SMEM_BYTES);
    cudaFuncSetAttribute(route_kernel<2>, cudaFuncAttributeMaxDynamicSharedMemorySize, SMEM_BYTES);

    void* sptr = nullptr;
    cudaGetSymbolAddress(&sptr, g_s);
    cudaMemsetAsync(sptr, 0, sizeof(float) * 3 * BSZ * JCAPS * MDIM);

    route_kernel<0><<<sm, THREADS, SMEM_BYTES>>>(x, W);
    route_kernel<1><<<sm, THREADS, SMEM_BYTES>>>(x, W);
    route_kernel<2><<<sm, THREADS, SMEM_BYTES>>>(x, W);
    final_squash_kernel<<<16, 32>>>((float*)d_out);
}

// round 8
// speedup vs baseline: 2.9991x; 1.1228x over previous
#include <cuda_runtime.h>

#define BSZ 64
#define ICAPS 8192
#define JCAPS 8
#define NDIM 8
#define MDIM 16

#define CI 8
#define NCHUNKS (ICAPS / CI)       /* 1024 */
#define THREADS 512

#define W_FLOATS (CI * 1024)       /* 8192 per buffer: [ci][n][j^(n&1)][m16] */
#define X_STRIDE 68                /* non-duplicated x row: 64 data + 4 pad */
#define X_FLOATS (BSZ * X_STRIDE)  /* 4352 */
#define SMEM_FLOATS (2 * W_FLOATS + X_FLOATS)       /* 20736 */
#define SMEM_BYTES (SMEM_FLOATS * 4)                /* 82944 B */

__device__ float g_s[3][BSZ * JCAPS * MDIM];   // stage-wise s accumulators

typedef unsigned long long u64;

__device__ __forceinline__ u64 pk2(float a, float b) {
    u64 r; asm("mov.b64 %0, {%1, %2};" : "=l"(r) : "f"(a), "f"(b)); return r;
}
__device__ __forceinline__ void upk2(u64 v, float& a, float& b) {
    asm("mov.b64 {%0, %1}, %2;" : "=f"(a), "=f"(b) : "l"(v));
}
__device__ __forceinline__ u64 mul2(u64 a, u64 b) {
    u64 r; asm("mul.rn.f32x2 %0, %1, %2;" : "=l"(r) : "l"(a), "l"(b)); return r;
}
__device__ __forceinline__ void fma2(u64& d, u64 a, u64 b) {
    asm("fma.rn.f32x2 %0, %1, %2, %0;" : "+l"(d) : "l"(a), "l"(b));
}
__device__ __forceinline__ void add2(u64& d, u64 a) {
    asm("add.rn.f32x2 %0, %1, %0;" : "+l"(d) : "l"(a));
}
__device__ __forceinline__ void lds2(u64& a, u64& b, unsigned addr) {
    asm volatile("ld.shared.v2.b64 {%0, %1}, [%2];" : "=l"(a), "=l"(b) : "r"(addr));
}
__device__ __forceinline__ void cpasync16(unsigned dst, const void* src) {
    asm volatile("cp.async.cg.shared.global [%0], [%1], 16;" :: "r"(dst), "l"(src));
}
__device__ __forceinline__ void cpcommit() { asm volatile("cp.async.commit_group;"); }
__device__ __forceinline__ void cpwait0()  { asm volatile("cp.async.wait_group 0;" ::: "memory"); }

// Stage one chunk's W via cp.async with transpose+swizzle scatter (validated R4-R7).
// global [ci][j][n][m16] -> smem [ci][n][j^(n&1)][m16].
__device__ __forceinline__ void stage_W_async(unsigned wbuf, const float* __restrict__ W,
                                              int ch, int tid)
{
    const float* src = W + (size_t)ch * W_FLOATS;
    #pragma unroll
    for (int q = 0; q < 4; q++) {
        const int idx = (tid + q * THREADS) * 4;      // float index, 16B granule
        const int ci = idx >> 10;
        const int r  = idx & 1023;
        const int j  = r >> 7;
        const int n  = (r >> 4) & 7;
        const int m  = r & 15;                        // 0,4,8,12
        const unsigned dst = wbuf +
            (unsigned)((ci << 10) + (n << 7) + (((j ^ (n & 1))) << 4) + m) * 4u;
        cpasync16(dst, src + idx);
    }
}

// STAGE: 0 -> uniform-c contraction (no routing); 1,2 -> full routing.
template <int STAGE>
__global__ __launch_bounds__(THREADS, 1)
void route_kernel(const float* __restrict__ x, const float* __restrict__ W)
{
    extern __shared__ float sh[];
    float* xs = sh + 2 * W_FLOATS;

    const int tid  = threadIdx.x;
    const int lane = tid & 31;
    const int w    = tid >> 5;
    const int j    = lane >> 2;     // out-cap 0..7
    const int mq   = lane & 3;      // m-quad 0..3
    const int b0   = w * 4;         // warp owns batches b0..b0+3

    // ---- vsum = sum_{st<STAGE} squash(g_s[st]) for this lane's (4 batches, j, mq) ----
    u64 vp[4][2];
    if (STAGE > 0) {
        #pragma unroll
        for (int bb = 0; bb < 4; bb++) {
            float v0 = 0.f, v1 = 0.f, v2v = 0.f, v3 = 0.f;
            #pragma unroll
            for (int st = 0; st < STAGE; ++st) {
                const float4 s4 = __ldcg(reinterpret_cast<const float4*>(
                    &g_s[st][((b0 + bb) * JCAPS + j) * MDIM + mq * 4]));
                float sq = s4.x * s4.x;
                sq = fmaf(s4.y, s4.y, sq);
                sq = fmaf(s4.z, s4.z, sq);
                sq = fmaf(s4.w, s4.w, sq);
                sq += __shfl_xor_sync(0xffffffffu, sq, 1);
                sq += __shfl_xor_sync(0xffffffffu, sq, 2);   // norm^2 over all 16 m
                const float sc = sqrtf(sq) / (1.0f + sq);    // squash scale
                v0 = fmaf(sc, s4.x, v0); v1 = fmaf(sc, s4.y, v1);
                v2v = fmaf(sc, s4.z, v2v); v3 = fmaf(sc, s4.w, v3);
            }
            vp[bb][0] = pk2(v0, v1);
            vp[bb][1] = pk2(v2v, v3);
        }
    }

    u64 sacc[4][2];
    #pragma unroll
    for (int bb = 0; bb < 4; bb++) { sacc[bb][0] = 0ull; sacc[bb][1] = 0ull; }

    const unsigned shbase = (unsigned)__cvta_generic_to_shared(sh);
    const unsigned xsbase = shbase + 2u * W_FLOATS * 4u;
    const unsigned wofs_e = (unsigned)((j * 16) + mq * 4) * 4u;        // even n
    const unsigned wofs_o = (unsigned)(((j ^ 1) * 16) + mq * 4) * 4u;  // odd n (XOR swizzle)

    // ---- double-buffered-W chunk loop (structure identical to validated R5/R7) ----
    int ch = blockIdx.x;
    int p  = 0;
    float4 xreg[2];
    stage_W_async(shbase, W, ch, tid);
    cpcommit();
    #pragma unroll
    for (int q = 0; q < 2; q++) {
        const int idx4 = tid + q * THREADS;
        const int b = idx4 >> 4;
        const int k = (idx4 & 15) * 4;
        xreg[q] = __ldcg(reinterpret_cast<const float4*>(
            &x[(size_t)b * (ICAPS * NDIM) + (size_t)ch * (CI * NDIM) + k]));
    }
    bool first = true;

    while (true) {
        if (!first) __syncthreads();
        cpwait0();
        // store x plain (non-duplicated)
        #pragma unroll
        for (int q = 0; q < 2; q++) {
            const int idx4 = tid + q * THREADS;
            const int b = idx4 >> 4;
            const int k = (idx4 & 15) * 4;
            *reinterpret_cast<float4*>(xs + b * X_STRIDE + k) = xreg[q];
        }
        __syncthreads();

        const int chn = ch + (int)gridDim.x;
        const bool have_next = (chn < NCHUNKS);
        if (have_next) {
            stage_W_async(shbase + (unsigned)(p ^ 1) * (W_FLOATS * 4u), W, chn, tid);
            cpcommit();
            #pragma unroll
            for (int q = 0; q < 2; q++) {
                const int idx4 = tid + q * THREADS;
                const int b = idx4 >> 4;
                const int k = (idx4 & 15) * 4;
                xreg[q] = __ldcg(reinterpret_cast<const float4*>(
                    &x[(size_t)b * (ICAPS * NDIM) + (size_t)chn * (CI * NDIM) + k]));
            }
        }

        // ---- compute this chunk (buffer p) ----
        const unsigned wb = shbase + (unsigned)p * (W_FLOATS * 4u);
        const unsigned we = wb + wofs_e;
        const unsigned wo = wb + wofs_o;

        #pragma unroll 1
        for (int ii = 0; ii < CI; ++ii) {
            u64 wp[8][2];
            #pragma unroll
            for (int n = 0; n < 8; n++) {
                const unsigned a = ((n & 1) ? wo : we) + (unsigned)(ii * 4096 + n * 512);
                lds2(wp[n][0], wp[n][1], a);
            }
            #pragma unroll
            for (int bb = 0; bb < 4; bb++) {
                // x[b, i, 0..7]: 32 B, broadcast (all lanes same address)
                const unsigned xa = xsbase + (unsigned)((b0 + bb) * X_STRIDE + ii * 8) * 4u;
                u64 xq[4];
                lds2(xq[0], xq[1], xa);
                lds2(xq[2], xq[3], xa + 16);
                float xf[8];
                upk2(xq[0], xf[0], xf[1]);   // register-pair aliasing (no SASS cost)
                upk2(xq[1], xf[2], xf[3]);
                upk2(xq[2], xf[4], xf[5]);
                upk2(xq[3], xf[6], xf[7]);

                u64 xd = pk2(xf[0], xf[0]);  // dup built in regs, used twice, dies
                u64 uh0 = mul2(wp[0][0], xd);
                u64 uh1 = mul2(wp[0][1], xd);
                #pragma unroll
                for (int n = 1; n < 8; n++) {
                    xd = pk2(xf[n], xf[n]);
                    fma2(uh0, wp[n][0], xd);
                    fma2(uh1, wp[n][1], xd);
                }

                if (STAGE == 0) {
                    // b == 0 -> c exactly 1/8 for all j: plain accumulation, scaled at flush
                    add2(sacc[bb][0], uh0);
                    add2(sacc[bb][1], uh1);
                } else {
                    // logit = dot(vsum, u_hat); |logit| < 1 so no max subtraction
                    u64 pp = mul2(uh0, vp[bb][0]);
                    fma2(pp, uh1, vp[bb][1]);
                    float plo, phi; upk2(pp, plo, phi);
                    float pl = plo + phi;
                    pl += __shfl_xor_sync(0xffffffffu, pl, 1);
                    pl += __shfl_xor_sync(0xffffffffu, pl, 2);
                    const float e = __expf(pl);
                    float sm = e;
                    sm += __shfl_xor_sync(0xffffffffu, sm, 4);
                    sm += __shfl_xor_sync(0xffffffffu, sm, 8);
                    sm += __shfl_xor_sync(0xffffffffu, sm, 16);
                    const float c = __fdividef(e, sm);
                    const u64 c2 = pk2(c, c);
                    fma2(sacc[bb][0], c2, uh0);
                    fma2(sacc[bb][1], c2, uh1);
                }
            }
        }

        if (!have_next) break;
        ch = chn;
        p ^= 1;
        first = false;
    }

    // ---- flush this warp's disjoint (b, j, mq) partials ----
    const float scale = (STAGE == 0) ? 0.125f : 1.0f;
    float* sout = &g_s[STAGE][0];
    #pragma unroll
    for (int bb = 0; bb < 4; bb++) {
        const int base = ((b0 + bb) * JCAPS + j) * MDIM + mq * 4;
        float a0, a1, a2, a3;
        upk2(sacc[bb][0], a0, a1);
        upk2(sacc[bb][1], a2, a3);
        atomicAdd(&sout[base + 0], scale * a0);
        atomicAdd(&sout[base + 1], scale * a1);
        atomicAdd(&sout[base + 2], scale * a2);
        atomicAdd(&sout[base + 3], scale * a3);
    }
}

// out = squash(s3)
__global__ void final_squash_kernel(float* __restrict__ out)
{
    const int t = blockIdx.x * blockDim.x + threadIdx.x;   // 0..511
    const int b = t >> 3;
    const int j = t & 7;
    const float* sp = &g_s[2][(b * JCAPS + j) * MDIM];
    float sv[MDIM];
    float sn = 0.0f;
    #pragma unroll
    for (int q = 0; q < 4; q++) {
        const float4 tt = __ldcg(reinterpret_cast<const float4*>(sp + q * 4));
        sv[q*4+0] = tt.x; sv[q*4+1] = tt.y; sv[q*4+2] = tt.z; sv[q*4+3] = tt.w;
    }
    #pragma unroll
    for (int m = 0; m < MDIM; m++) sn = fmaf(sv[m], sv[m], sn);
    const float scale = sqrtf(sn) / (1.0f + sn);
    #pragma unroll
    for (int m = 0; m < MDIM; m++) out[(b * JCAPS + j) * MDIM + m] = scale * sv[m];
}

extern "C" void kernel_launch(void* const* d_in, const int* in_sizes, int n_in,
                              void* d_out, int out_size)
{
    const float* x = (const float*)d_in[0];
    const float* W = (const float*)d_in[1];
    if (n_in >= 2 && in_sizes[0] == 8388608 && in_sizes[1] == 4194304) {
        x = (const float*)d_in[1];
        W = (const float*)d_in[0];
    }

    int dev = 0;
    cudaGetDevice(&dev);
    int sm = 148;
    cudaDeviceGetAttribute(&sm, cudaDevAttrMultiProcessorCount, dev);
    if (sm < 1) sm = 1;
    if (sm > 512) sm = 512;

    cudaFuncSetAttribute(route_kernel<0>, cudaFuncAttributeMaxDynamicSharedMemorySize, SMEM_BYTES);
    cudaFuncSetAttribute(route_kernel<1>, cudaFuncAttributeMaxDynamicSharedMemorySize, SMEM_BYTES);
    cudaFuncSetAttribute(route_kernel<2>, cudaFuncAttributeMaxDynamicSharedMemorySize, SMEM_BYTES);

    void* sptr = nullptr;
    cudaGetSymbolAddress(&sptr, g_s);
    cudaMemsetAsync(sptr, 0, sizeof(float) * 3 * BSZ * JCAPS * MDIM);

    route_kernel<0><<<sm, THREADS, SMEM_BYTES>>>(x, W);
    route_kernel<1><<<sm, THREADS, SMEM_BYTES>>>(x, W);
    route_kernel<2><<<sm, THREADS, SMEM_BYTES>>>(x, W);
    final_squash_kernel<<<16, 32>>>((float*)d_out);
}

// round 9
// speedup vs baseline: 3.0128x; 1.0046x over previous
#include <cuda_runtime.h>

#define BSZ 64
#define ICAPS 8192
#define JCAPS 8
#define NDIM 8
#define MDIM 16

#define CI 8
#define NCHUNKS (ICAPS / CI)       /* 1024 */
#define THREADS 512

#define W_FLOATS (CI * 1024)       /* 8192 per buffer: [ci][n][j^(n&1)][m16] */
#define X_STRIDE 68                /* non-duplicated x row: 64 data + 4 pad */
#define X_FLOATS (BSZ * X_STRIDE)  /* 4352 */
#define SMEM_FLOATS (2 * W_FLOATS + X_FLOATS)       /* 20736 */
#define SMEM_BYTES (SMEM_FLOATS * 4)                /* 82944 B */

__device__ float g_s[3][BSZ * JCAPS * MDIM];   // stage-wise s accumulators

typedef unsigned long long u64;

__device__ __forceinline__ u64 pk2(float a, float b) {
    u64 r; asm("mov.b64 %0, {%1, %2};" : "=l"(r) : "f"(a), "f"(b)); return r;
}
__device__ __forceinline__ void upk2(u64 v, float& a, float& b) {
    asm("mov.b64 {%0, %1}, %2;" : "=f"(a), "=f"(b) : "l"(v));
}
__device__ __forceinline__ u64 mul2(u64 a, u64 b) {
    u64 r; asm("mul.rn.f32x2 %0, %1, %2;" : "=l"(r) : "l"(a), "l"(b)); return r;
}
__device__ __forceinline__ void fma2(u64& d, u64 a, u64 b) {
    asm("fma.rn.f32x2 %0, %1, %2, %0;" : "+l"(d) : "l"(a), "l"(b));
}
__device__ __forceinline__ void add2(u64& d, u64 a) {
    asm("add.rn.f32x2 %0, %1, %0;" : "+l"(d) : "l"(a));
}
__device__ __forceinline__ void lds2(u64& a, u64& b, unsigned addr) {
    asm volatile("ld.shared.v2.b64 {%0, %1}, [%2];" : "=l"(a), "=l"(b) : "r"(addr));
}
__device__ __forceinline__ void cpasync16(unsigned dst, const void* src) {
    asm volatile("cp.async.cg.shared.global [%0], [%1], 16;" :: "r"(dst), "l"(src));
}
__device__ __forceinline__ void cpcommit() { asm volatile("cp.async.commit_group;"); }
__device__ __forceinline__ void cpwait0()  { asm volatile("cp.async.wait_group 0;" ::: "memory"); }

// Stage one chunk's W via cp.async with transpose+swizzle scatter (validated R4-R8).
// global [ci][j][n][m16] -> smem [ci][n][j^(n&1)][m16].
__device__ __forceinline__ void stage_W_async(unsigned wbuf, const float* __restrict__ W,
                                              int ch, int tid)
{
    const float* src = W + (size_t)ch * W_FLOATS;
    #pragma unroll
    for (int q = 0; q < 4; q++) {
        const int idx = (tid + q * THREADS) * 4;      // float index, 16B granule
        const int ci = idx >> 10;
        const int r  = idx & 1023;
        const int j  = r >> 7;
        const int n  = (r >> 4) & 7;
        const int m  = r & 15;                        // 0,4,8,12
        const unsigned dst = wbuf +
            (unsigned)((ci << 10) + (n << 7) + (((j ^ (n & 1))) << 4) + m) * 4u;
        cpasync16(dst, src + idx);
    }
}

// STAGE: 0 -> uniform-c contraction (no routing); 1,2 -> full routing.
template <int STAGE>
__global__ __launch_bounds__(THREADS, 1)
void route_kernel(const float* __restrict__ x, const float* __restrict__ W)
{
    extern __shared__ float sh[];
    float* xs = sh + 2 * W_FLOATS;

    const int tid  = threadIdx.x;
    const int lane = tid & 31;
    const int w    = tid >> 5;
    const int j    = lane >> 2;     // out-cap 0..7
    const int mq   = lane & 3;      // m-quad 0..3
    const int b0   = w * 4;         // warp owns batches b0..b0+3

    // ---- vsum = sum_{st<STAGE} squash(g_s[st]) for this lane's (4 batches, j, mq) ----
    u64 vp[4][2];
    if (STAGE > 0) {
        #pragma unroll
        for (int bb = 0; bb < 4; bb++) {
            float v0 = 0.f, v1 = 0.f, v2v = 0.f, v3 = 0.f;
            #pragma unroll
            for (int st = 0; st < STAGE; ++st) {
                const float4 s4 = __ldcg(reinterpret_cast<const float4*>(
                    &g_s[st][((b0 + bb) * JCAPS + j) * MDIM + mq * 4]));
                float sq = s4.x * s4.x;
                sq = fmaf(s4.y, s4.y, sq);
                sq = fmaf(s4.z, s4.z, sq);
                sq = fmaf(s4.w, s4.w, sq);
                sq += __shfl_xor_sync(0xffffffffu, sq, 1);
                sq += __shfl_xor_sync(0xffffffffu, sq, 2);   // norm^2 over all 16 m
                const float sc = sqrtf(sq) / (1.0f + sq);    // squash scale
                v0 = fmaf(sc, s4.x, v0); v1 = fmaf(sc, s4.y, v1);
                v2v = fmaf(sc, s4.z, v2v); v3 = fmaf(sc, s4.w, v3);
            }
            vp[bb][0] = pk2(v0, v1);
            vp[bb][1] = pk2(v2v, v3);
        }
    }

    u64 sacc[4][2];
    #pragma unroll
    for (int bb = 0; bb < 4; bb++) { sacc[bb][0] = 0ull; sacc[bb][1] = 0ull; }

    const unsigned shbase = (unsigned)__cvta_generic_to_shared(sh);
    const unsigned xsbase = shbase + 2u * W_FLOATS * 4u;
    const unsigned wofs_e = (unsigned)((j * 16) + mq * 4) * 4u;        // even n
    const unsigned wofs_o = (unsigned)(((j ^ 1) * 16) + mq * 4) * 4u;  // odd n (XOR swizzle)

    // ---- double-buffered-W chunk loop (identical to validated R8) ----
    int ch = blockIdx.x;
    int p  = 0;
    float4 xreg[2];
    stage_W_async(shbase, W, ch, tid);
    cpcommit();
    #pragma unroll
    for (int q = 0; q < 2; q++) {
        const int idx4 = tid + q * THREADS;
        const int b = idx4 >> 4;
        const int k = (idx4 & 15) * 4;
        xreg[q] = __ldcg(reinterpret_cast<const float4*>(
            &x[(size_t)b * (ICAPS * NDIM) + (size_t)ch * (CI * NDIM) + k]));
    }
    bool first = true;

    while (true) {
        if (!first) __syncthreads();
        cpwait0();
        #pragma unroll
        for (int q = 0; q < 2; q++) {
            const int idx4 = tid + q * THREADS;
            const int b = idx4 >> 4;
            const int k = (idx4 & 15) * 4;
            *reinterpret_cast<float4*>(xs + b * X_STRIDE + k) = xreg[q];
        }
        __syncthreads();

        const int chn = ch + (int)gridDim.x;
        const bool have_next = (chn < NCHUNKS);
        if (have_next) {
            stage_W_async(shbase + (unsigned)(p ^ 1) * (W_FLOATS * 4u), W, chn, tid);
            cpcommit();
            #pragma unroll
            for (int q = 0; q < 2; q++) {
                const int idx4 = tid + q * THREADS;
                const int b = idx4 >> 4;
                const int k = (idx4 & 15) * 4;
                xreg[q] = __ldcg(reinterpret_cast<const float4*>(
                    &x[(size_t)b * (ICAPS * NDIM) + (size_t)chn * (CI * NDIM) + k]));
            }
        }

        // ---- compute this chunk (buffer p), phase-structured for ILP ----
        const unsigned wb = shbase + (unsigned)p * (W_FLOATS * 4u);
        const unsigned we = wb + wofs_e;
        const unsigned wo = wb + wofs_o;

        #pragma unroll 1
        for (int ii = 0; ii < CI; ++ii) {
            // Phase 0: x for all 4 bb (broadcast loads, high MLP)
            float xf[4][8];
            #pragma unroll
            for (int bb = 0; bb < 4; bb++) {
                const unsigned xa = xsbase + (unsigned)((b0 + bb) * X_STRIDE + ii * 8) * 4u;
                u64 t0, t1, t2, t3;
                lds2(t0, t1, xa);
                lds2(t2, t3, xa + 16);
                upk2(t0, xf[bb][0], xf[bb][1]);
                upk2(t1, xf[bb][2], xf[bb][3]);
                upk2(t2, xf[bb][4], xf[bb][5]);
                upk2(t3, xf[bb][6], xf[bb][7]);
            }

            // Phase 1: stream W by n; apply each pair to all 4 bb, then discard
            u64 uh[4][2];
            {
                u64 w0, w1;
                lds2(w0, w1, we + (unsigned)(ii * 4096));
                #pragma unroll
                for (int bb = 0; bb < 4; bb++) {
                    const u64 xd = pk2(xf[bb][0], xf[bb][0]);
                    uh[bb][0] = mul2(w0, xd);
                    uh[bb][1] = mul2(w1, xd);
                }
            }
            #pragma unroll
            for (int n = 1; n < 8; n++) {
                u64 w0, w1;
                lds2(w0, w1, ((n & 1) ? wo : we) + (unsigned)(ii * 4096 + n * 512));
                #pragma unroll
                for (int bb = 0; bb < 4; bb++) {
                    const u64 xd = pk2(xf[bb][n], xf[bb][n]);
                    fma2(uh[bb][0], w0, xd);
                    fma2(uh[bb][1], w1, xd);
                }
            }

            if (STAGE == 0) {
                #pragma unroll
                for (int bb = 0; bb < 4; bb++) {
                    add2(sacc[bb][0], uh[bb][0]);
                    add2(sacc[bb][1], uh[bb][1]);
                }
            } else {
                // Phase 2: 4 softmaxes, chains interleaved 4-wide
                float pl[4];
                #pragma unroll
                for (int bb = 0; bb < 4; bb++) {
                    u64 pp = mul2(uh[bb][0], vp[bb][0]);
                    fma2(pp, uh[bb][1], vp[bb][1]);
                    float plo, phi; upk2(pp, plo, phi);
                    pl[bb] = plo + phi;
                }
                #pragma unroll
                for (int bb = 0; bb < 4; bb++) pl[bb] += __shfl_xor_sync(0xffffffffu, pl[bb], 1);
                #pragma unroll
                for (int bb = 0; bb < 4; bb++) pl[bb] += __shfl_xor_sync(0xffffffffu, pl[bb], 2);
                float e[4], sm[4];
                #pragma unroll
                for (int bb = 0; bb < 4; bb++) { e[bb] = __expf(pl[bb]); sm[bb] = e[bb]; }
                #pragma unroll
                for (int bb = 0; bb < 4; bb++) sm[bb] += __shfl_xor_sync(0xffffffffu, sm[bb], 4);
                #pragma unroll
                for (int bb = 0; bb < 4; bb++) sm[bb] += __shfl_xor_sync(0xffffffffu, sm[bb], 8);
                #pragma unroll
                for (int bb = 0; bb < 4; bb++) sm[bb] += __shfl_xor_sync(0xffffffffu, sm[bb], 16);
                #pragma unroll
                for (int bb = 0; bb < 4; bb++) {
                    const float c = __fdividef(e[bb], sm[bb]);
                    const u64 c2 = pk2(c, c);
                    fma2(sacc[bb][0], c2, uh[bb][0]);
                    fma2(sacc[bb][1], c2, uh[bb][1]);
                }
            }
        }

        if (!have_next) break;
        ch = chn;
        p ^= 1;
        first = false;
    }

    // ---- flush this warp's disjoint (b, j, mq) partials ----
    const float scale = (STAGE == 0) ? 0.125f : 1.0f;
    float* sout = &g_s[STAGE][0];
    #pragma unroll
    for (int bb = 0; bb < 4; bb++) {
        const int base = ((b0 + bb) * JCAPS + j) * MDIM + mq * 4;
        float a0, a1, a2, a3;
        upk2(sacc[bb][0], a0, a1);
        upk2(sacc[bb][1], a2, a3);
        atomicAdd(&sout[base + 0], scale * a0);
        atomicAdd(&sout[base + 1], scale * a1);
        atomicAdd(&sout[base + 2], scale * a2);
        atomicAdd(&sout[base + 3], scale * a3);
    }
}

// out = squash(s3)
__global__ void final_squash_kernel(float* __restrict__ out)
{
    const int t = blockIdx.x * blockDim.x + threadIdx.x;   // 0..511
    const int b = t >> 3;
    const int j = t & 7;
    const float* sp = &g_s[2][(b * JCAPS + j) * MDIM];
    float sv[MDIM];
    float sn = 0.0f;
    #pragma unroll
    for (int q = 0; q < 4; q++) {
        const float4 tt = __ldcg(reinterpret_cast<const float4*>(sp + q * 4));
        sv[q*4+0] = tt.x; sv[q*4+1] = tt.y; sv[q*4+2] = tt.z; sv[q*4+3] = tt.w;
    }
    #pragma unroll
    for (int m = 0; m < MDIM; m++) sn = fmaf(sv[m], sv[m], sn);
    const float scale = sqrtf(sn) / (1.0f + sn);
    #pragma unroll
    for (int m = 0; m < MDIM; m++) out[(b * JCAPS + j) * MDIM + m] = scale * sv[m];
}

extern "C" void kernel_launch(void* const* d_in, const int* in_sizes, int n_in,
                              void* d_out, int out_size)
{
    const float* x = (const float*)d_in[0];
    const float* W = (const float*)d_in[1];
    if (n_in >= 2 && in_sizes[0] == 8388608 && in_sizes[1] == 4194304) {
        x = (const float*)d_in[1];
        W = (const float*)d_in[0];
    }

    int dev = 0;
    cudaGetDevice(&dev);
    int sm = 148;
    cudaDeviceGetAttribute(&sm, cudaDevAttrMultiProcessorCount, dev);
    if (sm < 1) sm = 1;
    if (sm > 512) sm = 512;

    cudaFuncSetAttribute(route_kernel<0>, cudaFuncAttributeMaxDynamicSharedMemorySize, SMEM_BYTES);
    cudaFuncSetAttribute(route_kernel<1>, cudaFuncAttributeMaxDynamicSharedMemorySize, SMEM_BYTES);
    cudaFuncSetAttribute(route_kernel<2>, cudaFuncAttributeMaxDynamicSharedMemorySize, SMEM_BYTES);

    void* sptr = nullptr;
    cudaGetSymbolAddress(&sptr, g_s);
    cudaMemsetAsync(sptr, 0, sizeof(float) * 3 * BSZ * JCAPS * MDIM);

    route_kernel<0><<<sm, THREADS, SMEM_BYTES>>>(x, W);
    route_kernel<1><<<sm, THREADS, SMEM_BYTES>>>(x, W);
    route_kernel<2><<<sm, THREADS, SMEM_BYTES>>>(x, W);
    final_squash_kernel<<<16, 32>>>((float*)d_out);
}

// round 10
// speedup vs baseline: 3.1444x; 1.0437x over previous
#include <cuda_runtime.h>

#define BSZ 64
#define ICAPS 8192
#define JCAPS 8
#define NDIM 8
#define MDIM 16

#define CI 8
#define NCHUNKS (ICAPS / CI)       /* 1024 */
#define THREADS 512

#define W_FLOATS (CI * 1024)       /* 8192 per buffer: [ci][n][j^(n&1)][m16] */
#define X_STRIDE 68                /* non-duplicated x row: 64 data + 4 pad */
#define X_FLOATS (BSZ * X_STRIDE)  /* 4352 */
#define SMEM_FLOATS (2 * W_FLOATS + X_FLOATS)       /* 20736 */
#define SMEM_BYTES (SMEM_FLOATS * 4)                /* 82944 B */

__device__ float g_s[3][BSZ * JCAPS * MDIM];   // stage-wise s accumulators
__device__ float g_dummy[32];

typedef unsigned long long u64;

__device__ __forceinline__ u64 pk2(float a, float b) {
    u64 r; asm("mov.b64 %0, {%1, %2};" : "=l"(r) : "f"(a), "f"(b)); return r;
}
__device__ __forceinline__ void upk2(u64 v, float& a, float& b) {
    asm("mov.b64 {%0, %1}, %2;" : "=f"(a), "=f"(b) : "l"(v));
}
__device__ __forceinline__ u64 mul2(u64 a, u64 b) {
    u64 r; asm("mul.rn.f32x2 %0, %1, %2;" : "=l"(r) : "l"(a), "l"(b)); return r;
}
__device__ __forceinline__ void fma2(u64& d, u64 a, u64 b) {
    asm("fma.rn.f32x2 %0, %1, %2, %0;" : "+l"(d) : "l"(a), "l"(b));
}
__device__ __forceinline__ void add2(u64& d, u64 a) {
    asm("add.rn.f32x2 %0, %1, %0;" : "+l"(d) : "l"(a));
}
__device__ __forceinline__ void lds2(u64& a, u64& b, unsigned addr) {
    asm volatile("ld.shared.v2.b64 {%0, %1}, [%2];" : "=l"(a), "=l"(b) : "r"(addr));
}
__device__ __forceinline__ void cpasync16(unsigned dst, const void* src) {
    asm volatile("cp.async.cg.shared.global [%0], [%1], 16;" :: "r"(dst), "l"(src));
}
__device__ __forceinline__ void cpcommit() { asm volatile("cp.async.commit_group;"); }
__device__ __forceinline__ void cpwait0()  { asm volatile("cp.async.wait_group 0;" ::: "memory"); }

// Stage one chunk's W via cp.async with transpose+swizzle scatter (validated R4-R9).
// global [ci][j][n][m16] -> smem [ci][n][j^(n&1)][m16].
__device__ __forceinline__ void stage_W_async(unsigned wbuf, const float* __restrict__ W,
                                              int ch, int tid)
{
    const float* src = W + (size_t)ch * W_FLOATS;
    #pragma unroll
    for (int q = 0; q < 4; q++) {
        const int idx = (tid + q * THREADS) * 4;      // float index, 16B granule
        const int ci = idx >> 10;
        const int r  = idx & 1023;
        const int j  = r >> 7;
        const int n  = (r >> 4) & 7;
        const int m  = r & 15;                        // 0,4,8,12
        const unsigned dst = wbuf +
            (unsigned)((ci << 10) + (n << 7) + (((j ^ (n & 1))) << 4) + m) * 4u;
        cpasync16(dst, src + idx);
    }
}

// STAGE: 0 -> uniform-c contraction (no routing); 1,2 -> full routing.
template <int STAGE>
__global__ __launch_bounds__(THREADS, 1)
void route_kernel(const float* __restrict__ x, const float* __restrict__ W)
{
    extern __shared__ float sh[];
    float* xs = sh + 2 * W_FLOATS;

    const int tid  = threadIdx.x;
    const int lane = tid & 31;
    const int w    = tid >> 5;
    const int j    = lane >> 2;     // out-cap 0..7
    const int mq   = lane & 3;      // m-quad 0..3
    const int b0   = w * 4;         // warp owns batches b0..b0+3
    const bool q0  = (mq & 1) != 0;
    const bool q1  = (mq & 2) != 0;

    // ---- vsum = sum_{st<STAGE} squash(g_s[st]) for this lane's (4 batches, j, mq) ----
    u64 vp[4][2];
    if (STAGE > 0) {
        #pragma unroll
        for (int bb = 0; bb < 4; bb++) {
            float v0 = 0.f, v1 = 0.f, v2v = 0.f, v3 = 0.f;
            #pragma unroll
            for (int st = 0; st < STAGE; ++st) {
                const float4 s4 = __ldcg(reinterpret_cast<const float4*>(
                    &g_s[st][((b0 + bb) * JCAPS + j) * MDIM + mq * 4]));
                float sq = s4.x * s4.x;
                sq = fmaf(s4.y, s4.y, sq);
                sq = fmaf(s4.z, s4.z, sq);
                sq = fmaf(s4.w, s4.w, sq);
                sq += __shfl_xor_sync(0xffffffffu, sq, 1);
                sq += __shfl_xor_sync(0xffffffffu, sq, 2);   // norm^2 over all 16 m
                const float sc = sqrtf(sq) / (1.0f + sq);    // squash scale
                v0 = fmaf(sc, s4.x, v0); v1 = fmaf(sc, s4.y, v1);
                v2v = fmaf(sc, s4.z, v2v); v3 = fmaf(sc, s4.w, v3);
            }
            vp[bb][0] = pk2(v0, v1);
            vp[bb][1] = pk2(v2v, v3);
        }
    }

    u64 sacc[4][2];
    #pragma unroll
    for (int bb = 0; bb < 4; bb++) { sacc[bb][0] = 0ull; sacc[bb][1] = 0ull; }

    const unsigned shbase = (unsigned)__cvta_generic_to_shared(sh);
    const unsigned xsbase = shbase + 2u * W_FLOATS * 4u;
    const unsigned wofs_e = (unsigned)((j * 16) + mq * 4) * 4u;        // even n
    const unsigned wofs_o = (unsigned)(((j ^ 1) * 16) + mq * 4) * 4u;  // odd n (XOR swizzle)

    // ---- double-buffered-W chunk loop (identical to validated R8/R9) ----
    int ch = blockIdx.x;
    int p  = 0;
    float4 xreg[2];
    stage_W_async(shbase, W, ch, tid);
    cpcommit();
    #pragma unroll
    for (int q = 0; q < 2; q++) {
        const int idx4 = tid + q * THREADS;
        const int b = idx4 >> 4;
        const int k = (idx4 & 15) * 4;
        xreg[q] = __ldcg(reinterpret_cast<const float4*>(
            &x[(size_t)b * (ICAPS * NDIM) + (size_t)ch * (CI * NDIM) + k]));
    }
    bool first = true;

    while (true) {
        if (!first) __syncthreads();
        cpwait0();
        #pragma unroll
        for (int q = 0; q < 2; q++) {
            const int idx4 = tid + q * THREADS;
            const int b = idx4 >> 4;
            const int k = (idx4 & 15) * 4;
            *reinterpret_cast<float4*>(xs + b * X_STRIDE + k) = xreg[q];
        }
        __syncthreads();

        const int chn = ch + (int)gridDim.x;
        const bool have_next = (chn < NCHUNKS);
        if (have_next) {
            stage_W_async(shbase + (unsigned)(p ^ 1) * (W_FLOATS * 4u), W, chn, tid);
            cpcommit();
            #pragma unroll
            for (int q = 0; q < 2; q++) {
                const int idx4 = tid + q * THREADS;
                const int b = idx4 >> 4;
                const int k = (idx4 & 15) * 4;
                xreg[q] = __ldcg(reinterpret_cast<const float4*>(
                    &x[(size_t)b * (ICAPS * NDIM) + (size_t)chn * (CI * NDIM) + k]));
            }
        }

        // ---- compute this chunk (buffer p) ----
        const unsigned wb = shbase + (unsigned)p * (W_FLOATS * 4u);
        const unsigned we = wb + wofs_e;
        const unsigned wo = wb + wofs_o;

        #pragma unroll 1
        for (int ii = 0; ii < CI; ++ii) {
            // Phase 0: x for all 4 bb (broadcast loads)
            float xf[4][8];
            #pragma unroll
            for (int bb = 0; bb < 4; bb++) {
                const unsigned xa = xsbase + (unsigned)((b0 + bb) * X_STRIDE + ii * 8) * 4u;
                u64 t0, t1, t2, t3;
                lds2(t0, t1, xa);
                lds2(t2, t3, xa + 16);
                upk2(t0, xf[bb][0], xf[bb][1]);
                upk2(t1, xf[bb][2], xf[bb][3]);
                upk2(t2, xf[bb][4], xf[bb][5]);
                upk2(t3, xf[bb][6], xf[bb][7]);
            }

            // Phase 1: stream W by n; apply each pair to all 4 bb
            u64 uh[4][2];
            {
                u64 w0, w1;
                lds2(w0, w1, we + (unsigned)(ii * 4096));
                #pragma unroll
                for (int bb = 0; bb < 4; bb++) {
                    const u64 xd = pk2(xf[bb][0], xf[bb][0]);
                    uh[bb][0] = mul2(w0, xd);
                    uh[bb][1] = mul2(w1, xd);
                }
            }
            #pragma unroll
            for (int n = 1; n < 8; n++) {
                u64 w0, w1;
                lds2(w0, w1, ((n & 1) ? wo : we) + (unsigned)(ii * 4096 + n * 512));
                #pragma unroll
                for (int bb = 0; bb < 4; bb++) {
                    const u64 xd = pk2(xf[bb][n], xf[bb][n]);
                    fma2(uh[bb][0], w0, xd);
                    fma2(uh[bb][1], w1, xd);
                }
            }

            if (STAGE == 0) {
                #pragma unroll
                for (int bb = 0; bb < 4; bb++) {
                    add2(sacc[bb][0], uh[bb][0]);
                    add2(sacc[bb][1], uh[bb][1]);
                }
            } else {
                // Phase 2: TRANSPOSED softmax — mq-lane owns bb = mq.
                // Per-lane partial logits (lane's 4 m) for each bb:
                float pL[4];
                #pragma unroll
                for (int bb = 0; bb < 4; bb++) {
                    u64 pp = mul2(uh[bb][0], vp[bb][0]);
                    fma2(pp, uh[bb][1], vp[bb][1]);
                    float plo, phi; upk2(pp, plo, phi);
                    pL[bb] = plo + phi;
                }
                // transpose-reduce over mq lanes (xor 1 then xor 2):
                const float pm   = q1 ? (q0 ? pL[3] : pL[2]) : (q0 ? pL[1] : pL[0]); // p[mq]
                const float pmx1 = q1 ? (q0 ? pL[2] : pL[3]) : (q0 ? pL[0] : pL[1]); // p[mq^1]
                const float pmx2 = q1 ? (q0 ? pL[1] : pL[0]) : (q0 ? pL[3] : pL[2]); // p[mq^2]
                const float pmx3 = q1 ? (q0 ? pL[0] : pL[1]) : (q0 ? pL[2] : pL[3]); // p[mq^3]
                const float SA = pm   + __shfl_xor_sync(0xffffffffu, pmx1, 1);
                const float SB = pmx2 + __shfl_xor_sync(0xffffffffu, pmx3, 1);
                const float t  = SA + __shfl_xor_sync(0xffffffffu, SB, 2);  // full logit, bb = mq
                // one exp + one j-sum + one divide serve all 4 bb
                const float e = __expf(t);            // |logit| < 1: no max needed
                float sm = e;
                sm += __shfl_xor_sync(0xffffffffu, sm, 4);
                sm += __shfl_xor_sync(0xffffffffu, sm, 8);
                sm += __shfl_xor_sync(0xffffffffu, sm, 16);
                const float cm = __fdividef(e, sm);   // c for bb = mq
                // gather all 4 c's back to every lane, indexed by bb:
                const float g  = __shfl_xor_sync(0xffffffffu, cm, 2);
                const float cA = q1 ? g : cm;         // c[mq & 1]
                const float cB = q1 ? cm : g;         // c[(mq & 1) | 2]
                const float gA = __shfl_xor_sync(0xffffffffu, cA, 1);
                const float gB = __shfl_xor_sync(0xffffffffu, cB, 1);
                float cc[4];
                cc[0] = q0 ? gA : cA;
                cc[1] = q0 ? cA : gA;
                cc[2] = q0 ? gB : cB;
                cc[3] = q0 ? cB : gB;
                #pragma unroll
                for (int bb = 0; bb < 4; bb++) {
                    const u64 c2 = pk2(cc[bb], cc[bb]);
                    fma2(sacc[bb][0], c2, uh[bb][0]);
                    fma2(sacc[bb][1], c2, uh[bb][1]);
                }
            }
        }

        if (!have_next) break;
        ch = chn;
        p ^= 1;
        first = false;
    }

    // ---- flush this warp's disjoint (b, j, mq) partials ----
    const float scale = (STAGE == 0) ? 0.125f : 1.0f;
    float* sout = &g_s[STAGE][0];
    #pragma unroll
    for (int bb = 0; bb < 4; bb++) {
        const int base = ((b0 + bb) * JCAPS + j) * MDIM + mq * 4;
        float a0, a1, a2, a3;
        upk2(sacc[bb][0], a0, a1);
        upk2(sacc[bb][1], a2, a3);
        atomicAdd(&sout[base + 0], scale * a0);
        atomicAdd(&sout[base + 1], scale * a1);
        atomicAdd(&sout[base + 2], scale * a2);
        atomicAdd(&sout[base + 3], scale * a3);
    }
}

// out = squash(s3)
__global__ void final_squash_kernel(float* __restrict__ out)
{
    const int t = blockIdx.x * blockDim.x + threadIdx.x;   // 0..511
    const int b = t >> 3;
    const int j = t & 7;
    const float* sp = &g_s[2][(b * JCAPS + j) * MDIM];
    float sv[MDIM];
    float sn = 0.0f;
    #pragma unroll
    for (int q = 0; q < 4; q++) {
        const float4 tt = __ldcg(reinterpret_cast<const float4*>(sp + q * 4));
        sv[q*4+0] = tt.x; sv[q*4+1] = tt.y; sv[q*4+2] = tt.z; sv[q*4+3] = tt.w;
    }
    #pragma unroll
    for (int m = 0; m < MDIM; m++) sn = fmaf(sv[m], sv[m], sn);
    const float scale = sqrtf(sn) / (1.0f + sn);
    #pragma unroll
    for (int m = 0; m < MDIM; m++) out[(b * JCAPS + j) * MDIM + m] = scale * sv[m];
}

// Tiny dummy to shift ncu's capture slot (-s 5 -c 1) onto a route kernel.
__global__ void prof_pad_kernel()
{
    if (threadIdx.x < 32) g_dummy[threadIdx.x] = (float)threadIdx.x;
}

extern "C" void kernel_launch(void* const* d_in, const int* in_sizes, int n_in,
                              void* d_out, int out_size)
{
    const float* x = (const float*)d_in[0];
    const float* W = (const float*)d_in[1];
    if (n_in >= 2 && in_sizes[0] == 8388608 && in_sizes[1] == 4194304) {
        x = (const float*)d_in[1];
        W = (const float*)d_in[0];
    }

    int dev = 0;
    cudaGetDevice(&dev);
    int sm = 148;
    cudaDeviceGetAttribute(&sm, cudaDevAttrMultiProcessorCount, dev);
    if (sm < 1) sm = 1;
    if (sm > 512) sm = 512;

    cudaFuncSetAttribute(route_kernel<0>, cudaFuncAttributeMaxDynamicSharedMemorySize, SMEM_BYTES);
    cudaFuncSetAttribute(route_kernel<1>, cudaFuncAttributeMaxDynamicSharedMemorySize, SMEM_BYTES);
    cudaFuncSetAttribute(route_kernel<2>, cudaFuncAttributeMaxDynamicSharedMemorySize, SMEM_BYTES);

    void* sptr = nullptr;
    cudaGetSymbolAddress(&sptr, g_s);
    cudaMemsetAsync(sptr, 0, sizeof(float) * 3 * BSZ * JCAPS * MDIM);

    prof_pad_kernel<<<1, 32>>>();
    route_kernel<0><<<sm, THREADS, SMEM_BYTES>>>(x, W);
    route_kernel<1><<<sm, THREADS, SMEM_BYTES>>>(x, W);
    route_kernel<2><<<sm, THREADS, SMEM_BYTES>>>(x, W);
    final_squash_kernel<<<16, 32>>>((float*)d_out);
}